// round 15
// baseline (speedup 1.0000x reference)
#include <cuda_runtime.h>

#define NBLK 148
#define NTHR 1024
#define NWPC 32
#define NWARP (NBLK*NWPC)   // 4736
#define NL 6
#define DD 512
#define FF 2048
#define TD 1536
#define NBAR 36ULL

// ---------------- device scratch ----------------
__device__ __align__(16) float g_src35[35*DD];
__device__ __align__(16) float g_kv[NL*5*7*1024];
__device__ __align__(16) float g_q0[NL*5*DD];
__device__ __align__(16) float g_ctx5[NL*5*DD];
__device__ __align__(16) float g_vm[NL*5*DD];
__device__ __align__(16) float g_aggv[NL*DD];
__device__ __align__(16) float g_qkvS[6*TD];     // current layer rows 1..6 (q,k,v)
__device__ __align__(16) float g_kv0[1024];      // token0 k,v (current layer)
__device__ __align__(16) float g_msgN[6*DD];
__device__ __align__(16) float g_aggnraw[DD];
__device__ __align__(16) float g_hid[7*FF];      // [0,FF): up2; [FF,7FF): up1 rows1-6
__device__ __align__(16) float g_yraw[7*DD];     // row0: down2 RAW; rows1-6: down1 (bias+resid incl)
__device__ unsigned long long g_bar;

// ---------------- helpers ----------------
__device__ __forceinline__ float wred(float v) {
#pragma unroll
    for (int o = 16; o; o >>= 1) v += __shfl_xor_sync(0xffffffffu, v, o);
    return v;
}
__device__ __forceinline__ float d4(float4 a, float4 b) {
    return fmaf(a.x, b.x, fmaf(a.y, b.y, fmaf(a.z, b.z, a.w * b.w)));
}
__device__ __forceinline__ void gb_arrive() {
    __syncthreads();
    if (threadIdx.x == 0)
        asm volatile("red.release.gpu.add.u64 [%0], %1;" :: "l"(&g_bar), "l"(1ULL) : "memory");
}
__device__ __forceinline__ void gb_wait(unsigned long long base, int idx) {
    if (threadIdx.x == 0) {
        unsigned long long target = base + (unsigned long long)idx * NBLK;
        unsigned long long cur;
        for (;;) {
            asm volatile("ld.acquire.gpu.u64 %0, [%1];" : "=l"(cur) : "l"(&g_bar) : "memory");
            if (cur >= target) break;
            __nanosleep(64);
        }
    }
    __syncthreads();
}
// real L2 prefetch (ld.global.cg, dead regs)
__device__ __forceinline__ void pf_ld(const float* base, int nfloats, int gt) {
    const char* p = (const char*)base;
    int nlines = nfloats >> 5;
    for (int i = gt; i < nlines; i += NBLK*NTHR) {
        const char* q = p + (size_t)i*128;
        float a, b, c, d;
        asm volatile(
            "ld.global.cg.f32 %0, [%4];\n\t"
            "ld.global.cg.f32 %1, [%4+32];\n\t"
            "ld.global.cg.f32 %2, [%4+64];\n\t"
            "ld.global.cg.f32 %3, [%4+96];"
            : "=f"(a), "=f"(b), "=f"(c), "=f"(d) : "l"(q));
    }
}
__device__ __forceinline__ void cp4(float* dst, const float* src, int n) {
    float4* d4p = (float4*)dst;
    const float4* s4p = (const float4*)src;
    for (int i = threadIdx.x; i < (n >> 2); i += NTHR) d4p[i] = s4p[i];
}
__device__ __forceinline__ void ldw(const float* w, float4* wv) {
    const float4* wr = (const float4*)w;
    int lane = threadIdx.x & 31;
#pragma unroll
    for (int i = 0; i < 4; i++) wv[i] = __ldg(&wr[lane + 32*i]);
}
template<int K, int STR>
__device__ __forceinline__ void dotK(const float4* wv, const float* smbase, float* res) {
    int lane = threadIdx.x & 31;
    float acc[K];
#pragma unroll
    for (int k = 0; k < K; k++) {
        const float4* s4 = (const float4*)(smbase + k*STR);
        float a0 = d4(wv[0], s4[lane]);
        float a1 = d4(wv[1], s4[lane+32]);
        float a2 = d4(wv[2], s4[lane+64]);
        float a3 = d4(wv[3], s4[lane+96]);
        acc[k] = (a0 + a1) + (a2 + a3);
    }
#pragma unroll
    for (int o = 16; o; o >>= 1)
#pragma unroll
        for (int k = 0; k < K; k++)
            acc[k] += __shfl_xor_sync(0xffffffffu, acc[k], o);
#pragma unroll
    for (int k = 0; k < K; k++) res[k] = acc[k];
}
template<int NIT>
__device__ __forceinline__ float dot_long(const float* w, const float* smbase) {
    int lane = threadIdx.x & 31;
    const float4* wr = (const float4*)w;
    const float4* s4 = (const float4*)smbase;
    float a[4] = {0.f, 0.f, 0.f, 0.f};
#pragma unroll
    for (int i = 0; i < NIT; i += 4) {
        a[0] += d4(__ldg(&wr[lane + 32*(i+0)]), s4[lane + 32*(i+0)]);
        a[1] += d4(__ldg(&wr[lane + 32*(i+1)]), s4[lane + 32*(i+1)]);
        a[2] += d4(__ldg(&wr[lane + 32*(i+2)]), s4[lane + 32*(i+2)]);
        a[3] += d4(__ldg(&wr[lane + 32*(i+3)]), s4[lane + 32*(i+3)]);
    }
    return wred((a[0] + a[1]) + (a[2] + a[3]));
}
template<typename G>
__device__ __forceinline__ void ln_rowf(G get, const float* __restrict__ w,
                                        const float* __restrict__ b,
                                        float* __restrict__ out) {
    int lane = threadIdx.x & 31;
    float v[16]; float s = 0.f;
#pragma unroll
    for (int j = 0; j < 16; j++) { v[j] = get(j*32 + lane); s += v[j]; }
    s = wred(s);
    float mu = s * (1.f/512.f);
    float q = 0.f;
#pragma unroll
    for (int j = 0; j < 16; j++) { float d = v[j] - mu; q += d*d; }
    q = wred(q);
    float rs = rsqrtf(q * (1.f/512.f) + 1e-5f);
#pragma unroll
    for (int j = 0; j < 16; j++)
        out[j*32 + lane] = (v[j] - mu) * rs * w[j*32 + lane] + b[j*32 + lane];
}

__global__ void __launch_bounds__(NTHR, 1)
fused_kernel(const float* __restrict__ feat, const float* __restrict__ role,
             const float* __restrict__ in_w, const float* __restrict__ in_b,
             const float* __restrict__ out_w, const float* __restrict__ out_b,
             const float* __restrict__ ln1w, const float* __restrict__ ln1b,
             const float* __restrict__ ln2w, const float* __restrict__ ln2b,
             const float* __restrict__ ln3w, const float* __restrict__ ln3b,
             const float* __restrict__ ln4w, const float* __restrict__ ln4b,
             const float* __restrict__ f1w1, const float* __restrict__ f1b1,
             const float* __restrict__ f1w2, const float* __restrict__ f1b2,
             const float* __restrict__ f2w1, const float* __restrict__ f2b1,
             const float* __restrict__ f2w2, const float* __restrict__ f2b2,
             const float* __restrict__ a1w, const float* __restrict__ a1b,
             const float* __restrict__ a2w, const float* __restrict__ a2b,
             float* __restrict__ out)
{
    extern __shared__ float sm[];
    float* psx  = sm;          // 7*512: row0 persistent (t-path x); rows1-6 F4-local
    float* psh1 = sm + 3584;   // 6*512: LN1 output (s residual) for CURRENT layer
    float* psh0 = sm + 6656;   // 512:   LN3 output (t residual)
    float* sc   = sm + 7168;   // scratch (17920 floats)
    const int tid = threadIdx.x, lane = tid & 31, warp = tid >> 5;
    const int gw = blockIdx.x * NWPC + warp;
    const int gt = blockIdx.x * NTHR + tid;

    unsigned long long bbase = 0;
    if (tid == 0) {
        unsigned long long cur;
        asm volatile("ld.relaxed.gpu.u64 %0, [%1];" : "=l"(cur) : "l"(&g_bar));
        bbase = cur - (cur % (NBAR * (unsigned long long)NBLK));
    }
    int bi = 0;

    // ---- Phase A: src for batches 1..5 ----
    for (int i = gt; i < 35*DD; i += NBLK*NTHR) {
        int b5 = i / (7*DD); int rem = i % (7*DD); int s = rem / DD; int d = rem % DD;
        float v = feat[((b5+1)*7 + s)*DD + d];
        if (s > 0) v += role[((b5+1)*6 + (s-1))*DD + d];
        g_src35[i] = v;
    }
    gb_arrive();
    pf_ld(in_w, NL*TD*DD, gt);
    gb_wait(bbase, ++bi);

    // ---- P1: K,V for (l,b>=1,s) and Q(token0) ----
    cp4(sc, g_src35, 35*DD);
    __syncthreads();
    for (int t = gw; t < NL*1024 + NL*DD; t += NWARP) {
        float4 wv[4];
        {
            const float* rp = (t < NL*1024)
                ? in_w + ((size_t)(t >> 10)*TD + 512 + (t & 1023))*DD
                : in_w + ((size_t)((t - NL*1024) >> 9)*TD + ((t - NL*1024) & 511))*DD;
            ldw(rp, wv);
        }
        if (t < NL*1024) {
            int l = t >> 10, e = t & 1023;
            float bias = in_b[l*TD + 512 + e];
            float res[7];
#pragma unroll
            for (int g = 0; g < 5; g++) {
                dotK<7, DD>(wv, sc + g*7*DD, res);
                if (lane == 0)
#pragma unroll
                    for (int j = 0; j < 7; j++)
                        g_kv[((size_t)(l*5 + g)*7 + j)*1024 + e] = res[j] + bias;
            }
        } else {
            int t2 = t - NL*1024;
            int l = t2 >> 9, e = t2 & 511;
            float bias = in_b[l*TD + e];
            float res[5];
            dotK<5, 7*DD>(wv, sc, res);
            if (lane == 0)
#pragma unroll
                for (int j = 0; j < 5; j++)
                    g_q0[(l*5 + j)*DD + e] = res[j] + bias;
        }
    }
    gb_arrive();
    pf_ld(out_w, NL*DD*DD, gt);
    pf_ld(a1w, NL*DD*2560, gt);
    gb_wait(bbase, ++bi);

    // ---- P2a: attention token0 for (l, b>=1): 30 CTA tasks ----
    if (blockIdx.x < 30) {
        int l = blockIdx.x / 5, b5 = blockIdx.x % 5;
        float* sq = sc; float* sk = sc + DD; float* satt = sc + DD + 7*DD;
        const float* kvb = g_kv + (size_t)(l*5 + b5)*7*1024;
        cp4(sq, g_q0 + (l*5 + b5)*DD, DD);
        for (int i = tid; i < 7*DD; i += NTHR) { int s = i >> 9, d = i & 511; sk[i] = kvb[s*1024 + d]; }
        __syncthreads();
        if (tid < 56) {
            int h = tid / 7, s = tid % 7;
            float a = 0.f;
            for (int d = 0; d < 64; d++) a += sq[h*64 + d] * sk[s*DD + h*64 + d];
            satt[tid] = a * 0.125f;
        }
        __syncthreads();
        if (tid < 8) {
            float m = -1e30f;
            for (int s = 0; s < 7; s++) m = fmaxf(m, satt[tid*7 + s]);
            float e[7], su = 0.f;
            for (int s = 0; s < 7; s++) { e[s] = expf(satt[tid*7 + s] - m); su += e[s]; }
            for (int s = 0; s < 7; s++) satt[tid*7 + s] = e[s] / su;
        }
        __syncthreads();
        for (int ch = tid; ch < DD; ch += NTHR) {
            int h = ch >> 6;
            float a = 0.f;
            for (int s = 0; s < 7; s++) a += satt[h*7 + s] * kvb[s*1024 + 512 + ch];
            g_ctx5[(l*5 + b5)*DD + ch] = a;
        }
    }
    gb_arrive();
    gb_wait(bbase, ++bi);

    // ---- P2b: verb msgs ----
    cp4(sc, g_ctx5, 30*DD);
    __syncthreads();
    for (int t = gw; t < NL*DD; t += NWARP) {
        float4 wv[4];
        ldw(out_w + ((size_t)(t >> 9)*DD + (t & 511))*DD, wv);
        int l = t >> 9, e = t & 511;
        float bias = out_b[t];
        float res[5];
        dotK<5, DD>(wv, sc + l*5*DD, res);
        if (lane == 0)
#pragma unroll
            for (int j = 0; j < 5; j++)
                g_vm[(l*5 + j)*DD + e] = res[j] + bias;
    }
    gb_arrive();
    gb_wait(bbase, ++bi);

    // ---- P3: agg_verb ----
    cp4(sc, g_vm, 30*DD);
    __syncthreads();
    for (int t = gw; t < NL*DD; t += NWARP) {
        int l = t >> 9, e = t & 511;
        float a = dot_long<20>(a1w + ((size_t)l*DD + e)*2560, sc + l*5*DD);
        if (lane == 0) g_aggv[l*DD + e] = 1.f / (1.f + expf(-(a + a1b[l*DD + e])));
    }
    gb_arrive();
    pf_ld(f1w1, FF*DD, gt);
    gb_wait(bbase, ++bi);

    // ---- P4: seed layer 0 s-path (LN1, ssrc; qkvS_0 + up1_0) ----
    {
        float* ssrc = sc;   // 6*512
        if (warp < 6) {
            ln_rowf([&](int i){ return feat[(warp+1)*DD + i] + g_aggv[i]; },
                    ln1w, ln1b, psh1 + warp*DD);
        } else if (warp < 12) {
            int r = warp - 6;   // token r+1
            for (int j = 0; j < 16; j++) {
                int d = j*32 + lane;
                ssrc[r*DD + d] = feat[(r+1)*DD + d] + role[r*DD + d];
            }
        }
        __syncthreads();
        for (int t = gw; t < TD + FF; t += NWARP) {
            float4 wv[4];
            const float* rp = (t < TD) ? in_w + (size_t)t*DD
                                       : f1w1 + (size_t)(t - TD)*DD;
            ldw(rp, wv);
            if (t < TD) {
                float res[6];
                dotK<6, DD>(wv, ssrc, res);
                if (lane == 0) {
                    float bias = in_b[t];
#pragma unroll
                    for (int r = 0; r < 6; r++) g_qkvS[r*TD + t] = res[r] + bias;
                }
            } else {
                int e = t - TD;
                float res[6];
                dotK<6, DD>(wv, psh1, res);
                if (lane == 0) {
                    float bias = f1b1[e];
#pragma unroll
                    for (int r = 0; r < 6; r++)
                        g_hid[(r+1)*FF + e] = fmaxf(res[r] + bias, 0.f);
                }
            }
        }
    }
    gb_arrive();
    pf_ld(f1w2, DD*FF, gt);
    gb_wait(bbase, ++bi);

    // ================= layer loop =================
    for (int l = 0; l < NL; l++) {
        // ---- F1: LN4 -> psx row0 (redundant); kv0 (1024 tasks); zero yraw rows1-6 ----
        {
            if (warp == 0) {
                if (l == 0) {
                    for (int j = 0; j < 16; j++) psx[j*32 + lane] = feat[j*32 + lane];
                } else {
                    const float* fb = f2b2 + (l-1)*DD;
                    ln_rowf([&](int i){ return g_yraw[i] + fb[i] + psh0[i]; },
                            ln4w + (l-1)*DD, ln4b + (l-1)*DD, psx);
                }
            } else if (warp >= 13 && warp < 16) {
                int base = (warp - 13) * 1024;
                for (int j = 0; j < 32; j++) g_yraw[DD + base + j*32 + lane] = 0.f;
            }
            __syncthreads();
            for (int t = gw; t < 1024; t += NWARP) {
                float4 wv[4];
                ldw(in_w + ((size_t)l*TD + 512 + t)*DD, wv);
                float res[1];
                dotK<1, DD>(wv, psx, res);
                if (lane == 0) g_kv0[t] = res[0] + in_b[l*TD + 512 + t];
            }
        }
        gb_arrive();
        pf_ld(a2w + (size_t)l*DD*3072, DD*3072, gt);
        gb_wait(bbase, ++bi);

        // ---- F2: attention + msg (CTAs 0-31) | down1 (CTAs 32+) ----
        {
            if (blockIdx.x < 32) {
                float* sq   = sc;            // 6*512
                float* sk   = sc + 3072;     // 7*512
                float* sv   = sc + 6656;     // 7*512
                float* sctx = sc + 10240;    // 6*512
                float* satt = sc + 13312;    // 336
                for (int i = tid; i < 6*DD; i += NTHR) {
                    int r = i >> 9, d = i & 511;
                    sq[i] = g_qkvS[r*TD + d];
                }
                for (int i = tid; i < 7*DD; i += NTHR) {
                    int s = i >> 9, d = i & 511;
                    sk[i] = (s == 0) ? g_kv0[d] : g_qkvS[(s-1)*TD + 512 + d];
                    sv[i] = (s == 0) ? g_kv0[512 + d] : g_qkvS[(s-1)*TD + 1024 + d];
                }
                __syncthreads();
                for (int t = tid; t < 336; t += NTHR) {
                    int qi = t / 56, r = t % 56, h = r / 7, s = r % 7;
                    const float* qv = sq + qi*DD + h*64;
                    const float* kv = sk + s*DD + h*64;
                    float a0=0,a1=0,a2=0,a3=0;
#pragma unroll
                    for (int d = 0; d < 64; d += 4) {
                        a0 = fmaf(qv[d],   kv[d],   a0);
                        a1 = fmaf(qv[d+1], kv[d+1], a1);
                        a2 = fmaf(qv[d+2], kv[d+2], a2);
                        a3 = fmaf(qv[d+3], kv[d+3], a3);
                    }
                    satt[t] = ((a0+a1)+(a2+a3)) * 0.125f;
                }
                __syncthreads();
                if (tid < 48) {
                    int base = (tid/8)*56 + (tid%8)*7;
                    float m = -1e30f;
                    for (int s = 0; s < 7; s++) m = fmaxf(m, satt[base + s]);
                    float e[7], su = 0.f;
                    for (int s = 0; s < 7; s++) { e[s] = expf(satt[base + s] - m); su += e[s]; }
                    for (int s = 0; s < 7; s++) satt[base + s] = e[s] / su;
                }
                __syncthreads();
                for (int i = tid; i < 6*DD; i += NTHR) {
                    int qi = i >> 9, ch = i & 511, h = ch >> 6;
                    float a = 0.f;
                    for (int s = 0; s < 7; s++) a += satt[qi*56 + h*7 + s] * sv[s*DD + ch];
                    sctx[i] = a;
                }
                __syncthreads();
                if (warp < 16) {
                    int t = blockIdx.x * 16 + warp;   // 0..511
                    float4 wv[4];
                    ldw(out_w + ((size_t)l*DD + t)*DD, wv);
                    float res[6];
                    dotK<6, DD>(wv, sctx, res);
                    if (lane == 0) {
                        float bias = out_b[l*DD + t];
#pragma unroll
                        for (int r = 0; r < 6; r++) g_msgN[r*DD + t] = res[r] + bias;
                    }
                }
            } else {
                float* shid = sc;   // 6*2048
                cp4(shid, g_hid + FF, 6*FF);
                if (blockIdx.x == 140)
                    for (int i = tid; i < DD; i += NTHR) g_aggnraw[i] = 0.f;
                __syncthreads();
                const int nw2 = NWARP - 32*NWPC;
                for (int u = gw - 32*NWPC; u < 2048; u += nw2) {
                    int e = u & 511, s = u >> 9;
                    float4 wv[4];
                    ldw(f1w2 + ((size_t)l*DD + e)*FF + s*512, wv);
                    float res[6];
                    dotK<6, FF>(wv, shid + s*512, res);
                    if (lane == 0) {
                        float extra = (s == 0) ? f1b2[l*DD + e] : 0.f;
#pragma unroll
                        for (int r = 0; r < 6; r++) {
                            float add = res[r] + ((s == 0) ? (extra + psh1[r*DD + e]) : 0.f);
                            atomicAdd(&g_yraw[(r+1)*DD + e], add);
                        }
                    }
                }
            }
        }
        gb_arrive();
        pf_ld(f2w1 + (size_t)l*FF*DD, FF*DD, gt);
        if (l + 1 < NL) pf_ld(f1w1 + (size_t)(l+1)*FF*DD, FF*DD, gt);
        gb_wait(bbase, ++bi);

        // ---- F3: aggn (3072 tasks); zero yraw row0 ----
        {
            float* smsg = sc;   // 6*512
            cp4(smsg, g_msgN, 6*DD);
            if (blockIdx.x == 140)
                for (int i = tid; i < DD; i += NTHR) g_yraw[i] = 0.f;
            __syncthreads();
            for (int u = gw; u < 3072; u += NWARP) {
                int e = u & 511, s = u >> 9;
                float4 wv[4];
                ldw(a2w + ((size_t)l*DD + e)*3072 + s*512, wv);
                float res[1];
                dotK<1, DD>(wv, smsg + s*DD, res);
                if (lane == 0) atomicAdd(&g_aggnraw[e], res[0]);
            }
        }
        gb_arrive();
        if (l + 1 < NL) pf_ld(in_w + (size_t)(l+1)*TD*DD, TD*DD, gt);
        gb_wait(bbase, ++bi);

        // ---- F4: LN3+LN2; up2 + next layer's qkvS + up1 ----
        {
            float* ssrc = sc;   // 6*512
            if (warp == 0) {
                const float* ab = a2b + l*DD;
                ln_rowf([&](int i){
                            float a = g_aggnraw[i] + ab[i];
                            return psx[i] + 1.f / (1.f + expf(-a));
                        }, ln3w + l*DD, ln3b + l*DD, psh0);
            } else if (warp < 7) {
                float* dst = (l == NL-1) ? (out + warp*DD) : (psx + warp*DD);
                ln_rowf([&](int i){ return g_yraw[warp*DD + i]; },
                        ln2w + l*DD, ln2b + l*DD, dst);
            }
            __syncthreads();
            int ntask = 2048;
            if (l + 1 < NL) {
                if (warp < 6) {
                    ln_rowf([&](int i){ return psx[(warp+1)*DD + i] + g_aggv[(l+1)*DD + i]; },
                            ln1w + (l+1)*DD, ln1b + (l+1)*DD, psh1 + warp*DD);
                } else if (warp < 12) {
                    int r = warp - 6;
                    for (int j = 0; j < 16; j++) {
                        int d = j*32 + lane;
                        ssrc[r*DD + d] = psx[(r+1)*DD + d] + role[r*DD + d];
                    }
                }
                __syncthreads();
                ntask = 2048 + TD + FF;   // 5632
            }
            for (int t = gw; t < ntask; t += NWARP) {
                float4 wv[4];
                if (t < 2048) {
                    ldw(f2w1 + ((size_t)l*FF + t)*DD, wv);
                    float res[1];
                    dotK<1, DD>(wv, psh0, res);
                    if (lane == 0) g_hid[t] = fmaxf(res[0] + f2b1[l*FF + t], 0.f);
                } else if (t < 2048 + TD) {
                    int e = t - 2048;
                    ldw(in_w + ((size_t)(l+1)*TD + e)*DD, wv);
                    float res[6];
                    dotK<6, DD>(wv, ssrc, res);
                    if (lane == 0) {
                        float bias = in_b[(l+1)*TD + e];
#pragma unroll
                        for (int r = 0; r < 6; r++) g_qkvS[r*TD + e] = res[r] + bias;
                    }
                } else {
                    int e = t - 2048 - TD;
                    ldw(f1w1 + ((size_t)(l+1)*FF + e)*DD, wv);
                    float res[6];
                    dotK<6, DD>(wv, psh1, res);
                    if (lane == 0) {
                        float bias = f1b1[(l+1)*FF + e];
#pragma unroll
                        for (int r = 0; r < 6; r++)
                            g_hid[(r+1)*FF + e] = fmaxf(res[r] + bias, 0.f);
                    }
                }
            }
        }
        gb_arrive();
        pf_ld(f2w2 + (size_t)l*DD*FF, DD*FF, gt);
        gb_wait(bbase, ++bi);

        // ---- F5: down2 (2048 tasks, RAW partials) ----
        {
            float* shid0 = sc;   // 2048
            cp4(shid0, g_hid, FF);
            __syncthreads();
            for (int u = gw; u < 2048; u += NWARP) {
                int e = u & 511, s = u >> 9;
                float4 wv[4];
                ldw(f2w2 + ((size_t)l*DD + e)*FF + s*512, wv);
                float res[1];
                dotK<1, DD>(wv, shid0 + s*DD, res);
                if (lane == 0) atomicAdd(&g_yraw[e], res[0]);
            }
        }
        gb_arrive();
        if (l + 1 < NL) pf_ld(f1w2 + (size_t)(l+1)*DD*FF, DD*FF, gt);
        gb_wait(bbase, ++bi);
    }

    // ---- final output: row 0 = LN4_5 (rows 1-6 written in F4 of layer 5) ----
    if (blockIdx.x == 0 && warp == 0) {
        const float* fb = f2b2 + 5*DD;
        ln_rowf([&](int i){ return g_yraw[i] + fb[i] + psh0[i]; },
                ln4w + 5*DD, ln4b + 5*DD, out);
    }
}

#define SMEM_BYTES 102400

extern "C" void kernel_launch(void* const* d_in, const int* in_sizes, int n_in,
                              void* d_out, int out_size) {
    cudaFuncSetAttribute(fused_kernel, cudaFuncAttributeMaxDynamicSharedMemorySize, SMEM_BYTES);
    fused_kernel<<<NBLK, NTHR, SMEM_BYTES>>>(
        (const float*)d_in[0],  (const float*)d_in[1],
        (const float*)d_in[2],  (const float*)d_in[3],
        (const float*)d_in[4],  (const float*)d_in[5],
        (const float*)d_in[6],  (const float*)d_in[7],
        (const float*)d_in[8],  (const float*)d_in[9],
        (const float*)d_in[10], (const float*)d_in[11],
        (const float*)d_in[12], (const float*)d_in[13],
        (const float*)d_in[14], (const float*)d_in[15],
        (const float*)d_in[16], (const float*)d_in[17],
        (const float*)d_in[18], (const float*)d_in[19],
        (const float*)d_in[20], (const float*)d_in[21],
        (const float*)d_in[22], (const float*)d_in[23],
        (const float*)d_in[24], (const float*)d_in[25],
        (float*)d_out);
}

// round 16
// speedup vs baseline: 1.1135x; 1.1135x over previous
#include <cuda_runtime.h>

#define NBLK 148
#define NTHR 1024
#define NWPC 32
#define NWARP (NBLK*NWPC)   // 4736
#define NL 6
#define DD 512
#define FF 2048
#define TD 1536
#define NBAR 35ULL

// ---------------- device scratch ----------------
__device__ __align__(16) float g_src35[35*DD];
__device__ __align__(16) float g_kv[NL*5*7*1024];
__device__ __align__(16) float g_q0[NL*5*DD];
__device__ __align__(16) float g_ctx5[NL*5*DD];
__device__ __align__(16) float g_vm[NL*5*DD];
__device__ __align__(16) float g_aggv[NL*DD];
__device__ __align__(16) float g_qkv0[7*TD];
__device__ __align__(16) float g_msgN[6*DD];
__device__ __align__(16) float g_aggnraw[DD];
__device__ __align__(16) float g_hid[7*FF];   // [0,FF): up2; [FF,7FF): up1 rows1-6
__device__ __align__(16) float g_yraw[7*DD];  // row0: down2 RAW; rows1-6: down1 (bias+resid incl)
__device__ unsigned long long g_bar;

// ---------------- helpers ----------------
__device__ __forceinline__ float wred(float v) {
#pragma unroll
    for (int o = 16; o; o >>= 1) v += __shfl_xor_sync(0xffffffffu, v, o);
    return v;
}
__device__ __forceinline__ float d4(float4 a, float4 b) {
    return fmaf(a.x, b.x, fmaf(a.y, b.y, fmaf(a.z, b.z, a.w * b.w)));
}
__device__ __forceinline__ void gb_arrive() {
    __syncthreads();
    if (threadIdx.x == 0)
        asm volatile("red.release.gpu.add.u64 [%0], %1;" :: "l"(&g_bar), "l"(1ULL) : "memory");
}
__device__ __forceinline__ void gb_wait(unsigned long long base, int idx) {
    if (threadIdx.x == 0) {
        unsigned long long target = base + (unsigned long long)idx * NBLK;
        unsigned long long cur;
        for (;;) {
            asm volatile("ld.acquire.gpu.u64 %0, [%1];" : "=l"(cur) : "l"(&g_bar) : "memory");
            if (cur >= target) break;
            __nanosleep(64);
        }
    }
    __syncthreads();
}
// real L2 prefetch (ld.global.cg, dead regs)
__device__ __forceinline__ void pf_ld(const float* base, int nfloats, int gt) {
    const char* p = (const char*)base;
    int nlines = nfloats >> 5;
    for (int i = gt; i < nlines; i += NBLK*NTHR) {
        const char* q = p + (size_t)i*128;
        float a, b, c, d;
        asm volatile(
            "ld.global.cg.f32 %0, [%4];\n\t"
            "ld.global.cg.f32 %1, [%4+32];\n\t"
            "ld.global.cg.f32 %2, [%4+64];\n\t"
            "ld.global.cg.f32 %3, [%4+96];"
            : "=f"(a), "=f"(b), "=f"(c), "=f"(d) : "l"(q));
    }
}
__device__ __forceinline__ void cp4(float* dst, const float* src, int n) {
    float4* d4p = (float4*)dst;
    const float4* s4p = (const float4*)src;
    for (int i = threadIdx.x; i < (n >> 2); i += NTHR) d4p[i] = s4p[i];
}
// staggered copy: spreads per-line L2 pressure across slices
__device__ __forceinline__ void cp4s(float* dst, const float* src, int n) {
    int nq = n >> 2;
    int off = (int)((blockIdx.x * 61) % nq);
    float4* d4p = (float4*)dst;
    const float4* s4p = (const float4*)src;
    for (int c = threadIdx.x; c < nq; c += NTHR) {
        int j = c + off; if (j >= nq) j -= nq;
        d4p[j] = s4p[j];
    }
}
__device__ __forceinline__ void ldw(const float* w, float4* wv) {
    const float4* wr = (const float4*)w;
    int lane = threadIdx.x & 31;
#pragma unroll
    for (int i = 0; i < 4; i++) wv[i] = __ldg(&wr[lane + 32*i]);
}
template<int K, int STR>
__device__ __forceinline__ void dotK(const float4* wv, const float* smbase, float* res) {
    int lane = threadIdx.x & 31;
    float acc[K];
#pragma unroll
    for (int k = 0; k < K; k++) {
        const float4* s4 = (const float4*)(smbase + k*STR);
        float a0 = d4(wv[0], s4[lane]);
        float a1 = d4(wv[1], s4[lane+32]);
        float a2 = d4(wv[2], s4[lane+64]);
        float a3 = d4(wv[3], s4[lane+96]);
        acc[k] = (a0 + a1) + (a2 + a3);
    }
#pragma unroll
    for (int o = 16; o; o >>= 1)
#pragma unroll
        for (int k = 0; k < K; k++)
            acc[k] += __shfl_xor_sync(0xffffffffu, acc[k], o);
#pragma unroll
    for (int k = 0; k < K; k++) res[k] = acc[k];
}
template<int NIT>
__device__ __forceinline__ float dot_long(const float* w, const float* smbase) {
    int lane = threadIdx.x & 31;
    const float4* wr = (const float4*)w;
    const float4* s4 = (const float4*)smbase;
    float a[4] = {0.f, 0.f, 0.f, 0.f};
#pragma unroll
    for (int i = 0; i < NIT; i += 4) {
        a[0] += d4(__ldg(&wr[lane + 32*(i+0)]), s4[lane + 32*(i+0)]);
        a[1] += d4(__ldg(&wr[lane + 32*(i+1)]), s4[lane + 32*(i+1)]);
        a[2] += d4(__ldg(&wr[lane + 32*(i+2)]), s4[lane + 32*(i+2)]);
        a[3] += d4(__ldg(&wr[lane + 32*(i+3)]), s4[lane + 32*(i+3)]);
    }
    return wred((a[0] + a[1]) + (a[2] + a[3]));
}
template<typename G>
__device__ __forceinline__ void ln_rowf(G get, const float* __restrict__ w,
                                        const float* __restrict__ b,
                                        float* __restrict__ out) {
    int lane = threadIdx.x & 31;
    float v[16]; float s = 0.f;
#pragma unroll
    for (int j = 0; j < 16; j++) { v[j] = get(j*32 + lane); s += v[j]; }
    s = wred(s);
    float mu = s * (1.f/512.f);
    float q = 0.f;
#pragma unroll
    for (int j = 0; j < 16; j++) { float d = v[j] - mu; q += d*d; }
    q = wred(q);
    float rs = rsqrtf(q * (1.f/512.f) + 1e-5f);
#pragma unroll
    for (int j = 0; j < 16; j++)
        out[j*32 + lane] = (v[j] - mu) * rs * w[j*32 + lane] + b[j*32 + lane];
}

__global__ void __launch_bounds__(NTHR, 1)
fused_kernel(const float* __restrict__ feat, const float* __restrict__ role,
             const float* __restrict__ in_w, const float* __restrict__ in_b,
             const float* __restrict__ out_w, const float* __restrict__ out_b,
             const float* __restrict__ ln1w, const float* __restrict__ ln1b,
             const float* __restrict__ ln2w, const float* __restrict__ ln2b,
             const float* __restrict__ ln3w, const float* __restrict__ ln3b,
             const float* __restrict__ ln4w, const float* __restrict__ ln4b,
             const float* __restrict__ f1w1, const float* __restrict__ f1b1,
             const float* __restrict__ f1w2, const float* __restrict__ f1b2,
             const float* __restrict__ f2w1, const float* __restrict__ f2b1,
             const float* __restrict__ f2w2, const float* __restrict__ f2b2,
             const float* __restrict__ a1w, const float* __restrict__ a1b,
             const float* __restrict__ a2w, const float* __restrict__ a2b,
             float* __restrict__ out)
{
    extern __shared__ float sm[];
    float* psx   = sm;            // 7*512 persistent x rows
    float* psh1  = sm + 3584;     // 6*512 LN1 output
    float* psh0  = sm + 6656;     // 512   LN3 output
    float* srole = sm + 7168;     // 6*512 persistent role rows (batch 0)
    float* saggv = sm + 10240;    // 6*512 persistent aggv (all layers)
    float* sc    = sm + 13312;    // layer-loop scratch (14336 floats)
    float* scp   = sm + 7168;     // preamble scratch (20480 floats; clobbers srole/saggv)
    const int tid = threadIdx.x, lane = tid & 31, warp = tid >> 5;
    const int bid = blockIdx.x;
    const int gw = bid * NWPC + warp;
    const int gt = bid * NTHR + tid;

    unsigned long long bbase = 0;
    if (tid == 0) {
        unsigned long long cur;
        asm volatile("ld.relaxed.gpu.u64 %0, [%1];" : "=l"(cur) : "l"(&g_bar));
        bbase = cur - (cur % (NBAR * (unsigned long long)NBLK));
    }
    int bi = 0;

    // ---- Phase A: src for batches 1..5 ----
    for (int i = gt; i < 35*DD; i += NBLK*NTHR) {
        int b5 = i / (7*DD); int rem = i % (7*DD); int s = rem / DD; int d = rem % DD;
        float v = feat[((b5+1)*7 + s)*DD + d];
        if (s > 0) v += role[((b5+1)*6 + (s-1))*DD + d];
        g_src35[i] = v;
    }
    gb_arrive();
    pf_ld(in_w, NL*TD*DD, gt);
    gb_wait(bbase, ++bi);

    // ---- P1: K,V for (l,b>=1,s) and Q(token0) ----
    cp4s(scp, g_src35, 35*DD);
    __syncthreads();
    for (int t = gw; t < NL*1024 + NL*DD; t += NWARP) {
        float4 wv[4];
        {
            const float* rp = (t < NL*1024)
                ? in_w + ((size_t)(t >> 10)*TD + 512 + (t & 1023))*DD
                : in_w + ((size_t)((t - NL*1024) >> 9)*TD + ((t - NL*1024) & 511))*DD;
            ldw(rp, wv);
        }
        if (t < NL*1024) {
            int l = t >> 10, e = t & 1023;
            float bias = in_b[l*TD + 512 + e];
            float res[7];
#pragma unroll
            for (int g = 0; g < 5; g++) {
                dotK<7, DD>(wv, scp + g*7*DD, res);
                if (lane == 0)
#pragma unroll
                    for (int j = 0; j < 7; j++)
                        g_kv[((size_t)(l*5 + g)*7 + j)*1024 + e] = res[j] + bias;
            }
        } else {
            int t2 = t - NL*1024;
            int l = t2 >> 9, e = t2 & 511;
            float bias = in_b[l*TD + e];
            float res[5];
            dotK<5, 7*DD>(wv, scp, res);
            if (lane == 0)
#pragma unroll
                for (int j = 0; j < 5; j++)
                    g_q0[(l*5 + j)*DD + e] = res[j] + bias;
        }
    }
    gb_arrive();
    pf_ld(out_w, NL*DD*DD, gt);
    pf_ld(a1w, NL*DD*2560, gt);
    gb_wait(bbase, ++bi);

    // ---- P2a: attention token0 for (l, b>=1): 30 CTA tasks ----
    if (bid < 30) {
        int l = bid / 5, b5 = bid % 5;
        float* sq = scp; float* sk = scp + DD; float* satt = scp + DD + 7*DD;
        const float* kvb = g_kv + (size_t)(l*5 + b5)*7*1024;
        cp4(sq, g_q0 + (l*5 + b5)*DD, DD);
        for (int i = tid; i < 7*DD; i += NTHR) { int s = i >> 9, d = i & 511; sk[i] = kvb[s*1024 + d]; }
        __syncthreads();
        if (tid < 56) {
            int h = tid / 7, s = tid % 7;
            float a = 0.f;
            for (int d = 0; d < 64; d++) a += sq[h*64 + d] * sk[s*DD + h*64 + d];
            satt[tid] = a * 0.125f;
        }
        __syncthreads();
        if (tid < 8) {
            float m = -1e30f;
            for (int s = 0; s < 7; s++) m = fmaxf(m, satt[tid*7 + s]);
            float e[7], su = 0.f;
            for (int s = 0; s < 7; s++) { e[s] = expf(satt[tid*7 + s] - m); su += e[s]; }
            for (int s = 0; s < 7; s++) satt[tid*7 + s] = e[s] / su;
        }
        __syncthreads();
        for (int ch = tid; ch < DD; ch += NTHR) {
            int h = ch >> 6;
            float a = 0.f;
            for (int s = 0; s < 7; s++) a += satt[h*7 + s] * kvb[s*1024 + 512 + ch];
            g_ctx5[(l*5 + b5)*DD + ch] = a;
        }
    }
    gb_arrive();
    gb_wait(bbase, ++bi);

    // ---- P2b: verb msgs ----
    cp4s(scp, g_ctx5, 30*DD);
    __syncthreads();
    for (int t = gw; t < NL*DD; t += NWARP) {
        float4 wv[4];
        ldw(out_w + ((size_t)(t >> 9)*DD + (t & 511))*DD, wv);
        int l = t >> 9, e = t & 511;
        float bias = out_b[t];
        float res[5];
        dotK<5, DD>(wv, scp + l*5*DD, res);
        if (lane == 0)
#pragma unroll
            for (int j = 0; j < 5; j++)
                g_vm[(l*5 + j)*DD + e] = res[j] + bias;
    }
    gb_arrive();
    gb_wait(bbase, ++bi);

    // ---- P3: agg_verb ----
    cp4s(scp, g_vm, 30*DD);
    __syncthreads();
    for (int t = gw; t < NL*DD; t += NWARP) {
        int l = t >> 9, e = t & 511;
        float a = dot_long<20>(a1w + ((size_t)l*DD + e)*2560, scp + l*5*DD);
        if (lane == 0) g_aggv[l*DD + e] = 1.f / (1.f + expf(-(a + a1b[l*DD + e])));
    }
    gb_arrive();
    pf_ld(f1w1, FF*DD, gt);
    gb_wait(bbase, ++bi);

    // ---- load persistent smem state (psx, role, aggv) ----
    cp4(psx, feat, 7*DD);
    cp4s(srole, role, 6*DD);
    cp4s(saggv, g_aggv, NL*DD);
    __syncthreads();

    // ================= layer loop =================
    for (int l = 0; l < NL; l++) {
        // ---- F1: LN builds + qkv (all 7 tokens) + up1 ----
        {
            float* ssrc = sc;   // 7*512
            if (warp == 0) {
                if (l == 0) {
                    for (int j = 0; j < 16; j++) ssrc[j*32 + lane] = psx[j*32 + lane];
                } else {
                    const float* fb = f2b2 + (l-1)*DD;
                    ln_rowf([&](int i){ return g_yraw[i] + fb[i] + psh0[i]; },
                            ln4w + (l-1)*DD, ln4b + (l-1)*DD, ssrc);
                    for (int j = 0; j < 16; j++) psx[j*32 + lane] = ssrc[j*32 + lane];
                }
            } else if (warp < 7) {
                ln_rowf([&](int i){ return psx[warp*DD + i] + saggv[l*DD + i]; },
                        ln1w + l*DD, ln1b + l*DD, psh1 + (warp-1)*DD);
            } else if (warp < 13) {
                int r = warp - 6;   // 1..6
                for (int j = 0; j < 16; j++) {
                    int d = j*32 + lane;
                    ssrc[r*DD + d] = psx[r*DD + d] + srole[(r-1)*DD + d];
                }
            } else if (warp < 16) {
                int base = (warp - 13) * 1024;
                for (int j = 0; j < 32; j++) g_yraw[DD + base + j*32 + lane] = 0.f;
            }
            __syncthreads();
            for (int t = gw; t < TD + FF; t += NWARP) {
                float4 wv[4];
                {
                    const float* rp = (t < TD) ? in_w + ((size_t)l*TD + t)*DD
                                               : f1w1 + ((size_t)l*FF + (t - TD))*DD;
                    ldw(rp, wv);
                }
                if (t < TD) {
                    float res[7];
                    dotK<7, DD>(wv, ssrc, res);
                    if (lane == 0) {
                        float bias = in_b[l*TD + t];
#pragma unroll
                        for (int s = 0; s < 7; s++) g_qkv0[s*TD + t] = res[s] + bias;
                    }
                } else {
                    int e = t - TD;
                    float res[6];
                    dotK<6, DD>(wv, psh1, res);
                    if (lane == 0) {
                        float bias = f1b1[l*FF + e];
#pragma unroll
                        for (int r = 0; r < 6; r++)
                            g_hid[(r+1)*FF + e] = fmaxf(res[r] + bias, 0.f);
                    }
                }
            }
        }
        gb_arrive();
        pf_ld(a2w + (size_t)l*DD*3072, DD*3072, gt);
        pf_ld(f1w2 + (size_t)l*DD*FF, DD*FF, gt);
        gb_wait(bbase, ++bi);

        // ---- F2: attention + msg (CTAs 0-31) | down1 (CTAs 32+, 1-seg loads) ----
        {
            if (bid < 32) {
                float* sqkv = sc;            // 10752
                float* sctx = sc + 10752;    // 3072
                float* satt = sc + 13824;    // 336
                cp4s(sqkv, g_qkv0, 7*TD);
                __syncthreads();
                for (int t = tid; t < 336; t += NTHR) {
                    int qi = t / 56, r = t % 56, h = r / 7, s = r % 7;
                    const float* qv = sqkv + (qi+1)*TD + h*64;
                    const float* kv = sqkv + s*TD + 512 + h*64;
                    float a0=0,a1=0,a2=0,a3=0;
#pragma unroll
                    for (int d = 0; d < 64; d += 4) {
                        a0 = fmaf(qv[d],   kv[d],   a0);
                        a1 = fmaf(qv[d+1], kv[d+1], a1);
                        a2 = fmaf(qv[d+2], kv[d+2], a2);
                        a3 = fmaf(qv[d+3], kv[d+3], a3);
                    }
                    satt[t] = ((a0+a1)+(a2+a3)) * 0.125f;
                }
                __syncthreads();
                if (tid < 48) {
                    float m = -1e30f;
                    for (int s = 0; s < 7; s++) m = fmaxf(m, satt[tid*7 + s]);
                    float e[7], su = 0.f;
                    for (int s = 0; s < 7; s++) { e[s] = expf(satt[tid*7 + s] - m); su += e[s]; }
                    for (int s = 0; s < 7; s++) satt[tid*7 + s] = e[s] / su;
                }
                __syncthreads();
                for (int i = tid; i < 6*DD; i += NTHR) {
                    int qi = i >> 9, ch = i & 511, h = ch >> 6;
                    float a = 0.f;
                    for (int s = 0; s < 7; s++) a += satt[qi*56 + h*7 + s] * sqkv[s*TD + 1024 + ch];
                    sctx[i] = a;
                }
                __syncthreads();
                if (warp < 16) {
                    int t = bid * 16 + warp;   // 0..511
                    float4 wv[4];
                    ldw(out_w + ((size_t)l*DD + t)*DD, wv);
                    float res[6];
                    dotK<6, DD>(wv, sctx, res);
                    if (lane == 0) {
                        float bias = out_b[l*DD + t];
#pragma unroll
                        for (int r = 0; r < 6; r++) g_msgN[r*DD + t] = res[r] + bias;
                    }
                }
            } else {
                // down1: CTA (bid-32) covers u in [u0, u0+32) — single segment s0
                float* shloc = sc;   // 6*512
                int u0 = (bid - 32) * NWPC;
                int s0 = u0 >> 9;
                if (u0 < 2048) {
                    for (int i = tid; i < 6*512; i += NTHR) {
                        int r = i >> 9, d = i & 511;
                        shloc[i] = g_hid[FF + r*FF + s0*512 + d];
                    }
                }
                if (bid == 140)
                    for (int i = tid; i < DD; i += NTHR) g_aggnraw[i] = 0.f;
                __syncthreads();
                int u = u0 + warp;
                if (u < 2048) {
                    int e = u & 511;
                    float4 wv[4];
                    ldw(f1w2 + ((size_t)l*DD + e)*FF + s0*512, wv);
                    float res[6];
                    dotK<6, 512>(wv, shloc, res);
                    if (lane == 0) {
                        float extra = (s0 == 0) ? f1b2[l*DD + e] : 0.f;
#pragma unroll
                        for (int r = 0; r < 6; r++) {
                            float add = res[r] + ((s0 == 0) ? (extra + psh1[r*DD + e]) : 0.f);
                            atomicAdd(&g_yraw[(r+1)*DD + e], add);
                        }
                    }
                }
            }
        }
        gb_arrive();
        pf_ld(f2w1 + (size_t)l*FF*DD, FF*DD, gt);
        gb_wait(bbase, ++bi);

        // ---- F3: aggn (1-seg loads); zero yraw row0 ----
        {
            float* smloc = sc;   // 512
            int u0 = bid * NWPC;
            int s0 = u0 >> 9;
            if (u0 < 3072)
                for (int i = tid; i < 512; i += NTHR)
                    smloc[i] = g_msgN[s0*512 + i];
            if (bid == 140)
                for (int i = tid; i < DD; i += NTHR) g_yraw[i] = 0.f;
            __syncthreads();
            int u = gw;
            if (u < 3072) {
                int e = u & 511;
                float4 wv[4];
                ldw(a2w + ((size_t)l*DD + e)*3072 + s0*512, wv);
                float res[1];
                dotK<1, DD>(wv, smloc, res);
                if (lane == 0) atomicAdd(&g_aggnraw[e], res[0]);
            }
        }
        gb_arrive();
        if (l + 1 < NL) pf_ld(in_w + (size_t)(l+1)*TD*DD, TD*DD, gt);
        gb_wait(bbase, ++bi);

        // ---- F4: LN3 + LN2 + up2 ----
        {
            if (warp == 0) {
                const float* ab = a2b + l*DD;
                ln_rowf([&](int i){
                            float a = g_aggnraw[i] + ab[i];
                            return psx[i] + 1.f / (1.f + expf(-a));
                        }, ln3w + l*DD, ln3b + l*DD, psh0);
            } else if (warp < 7) {
                ln_rowf([&](int i){ return g_yraw[warp*DD + i]; },
                        ln2w + l*DD, ln2b + l*DD, psx + warp*DD);
            }
            __syncthreads();
            for (int t = gw; t < FF; t += NWARP) {
                float4 wv[4];
                ldw(f2w1 + ((size_t)l*FF + t)*DD, wv);
                float res[1];
                dotK<1, DD>(wv, psh0, res);
                if (lane == 0) g_hid[t] = fmaxf(res[0] + f2b1[l*FF + t], 0.f);
            }
        }
        gb_arrive();
        pf_ld(f2w2 + (size_t)l*DD*FF, DD*FF, gt);
        gb_wait(bbase, ++bi);

        // ---- F5: down2 (1-seg loads, RAW partials) ----
        {
            float* shloc = sc;   // 512
            int u0 = bid * NWPC;
            int s0 = u0 >> 9;
            if (u0 < 2048)
                for (int i = tid; i < 512; i += NTHR)
                    shloc[i] = g_hid[s0*512 + i];
            __syncthreads();
            int u = gw;
            if (u < 2048) {
                int e = u & 511;
                float4 wv[4];
                ldw(f2w2 + ((size_t)l*DD + e)*FF + s0*512, wv);
                float res[1];
                dotK<1, DD>(wv, shloc, res);
                if (lane == 0) atomicAdd(&g_yraw[e], res[0]);
            }
        }
        gb_arrive();
        if (l + 1 < NL) pf_ld(f1w1 + (size_t)(l+1)*FF*DD, FF*DD, gt);
        gb_wait(bbase, ++bi);
    }

    // ---- final output: LN4 row0, LN2 rows1-6 ----
    if (bid == 0 && warp < 7) {
        if (warp == 0) {
            const float* fb = f2b2 + 5*DD;
            ln_rowf([&](int i){ return g_yraw[i] + fb[i] + psh0[i]; },
                    ln4w + 5*DD, ln4b + 5*DD, out);
        } else {
            ln_rowf([&](int i){ return g_yraw[warp*DD + i]; },
                    ln2w + 5*DD, ln2b + 5*DD, out + warp*DD);
        }
    }
}

#define SMEM_BYTES 110592

extern "C" void kernel_launch(void* const* d_in, const int* in_sizes, int n_in,
                              void* d_out, int out_size) {
    cudaFuncSetAttribute(fused_kernel, cudaFuncAttributeMaxDynamicSharedMemorySize, SMEM_BYTES);
    fused_kernel<<<NBLK, NTHR, SMEM_BYTES>>>(
        (const float*)d_in[0],  (const float*)d_in[1],
        (const float*)d_in[2],  (const float*)d_in[3],
        (const float*)d_in[4],  (const float*)d_in[5],
        (const float*)d_in[6],  (const float*)d_in[7],
        (const float*)d_in[8],  (const float*)d_in[9],
        (const float*)d_in[10], (const float*)d_in[11],
        (const float*)d_in[12], (const float*)d_in[13],
        (const float*)d_in[14], (const float*)d_in[15],
        (const float*)d_in[16], (const float*)d_in[17],
        (const float*)d_in[18], (const float*)d_in[19],
        (const float*)d_in[20], (const float*)d_in[21],
        (const float*)d_in[22], (const float*)d_in[23],
        (const float*)d_in[24], (const float*)d_in[25],
        (float*)d_out);
}

// round 17
// speedup vs baseline: 1.1312x; 1.0159x over previous
#include <cuda_runtime.h>

#define NBLK 148
#define NTHR 1024
#define NWPC 32
#define NWARP (NBLK*NWPC)   // 4736
#define NL 6
#define DD 512
#define FF 2048
#define TD 1536
#define NBAR 35ULL

// ---------------- device scratch ----------------
__device__ __align__(16) float g_src35[35*DD];
__device__ __align__(16) float g_kv[NL*5*7*1024];
__device__ __align__(16) float g_q0[NL*5*DD];
__device__ __align__(16) float g_ctx5[NL*5*DD];
__device__ __align__(16) float g_vm[NL*5*DD];
__device__ __align__(16) float g_aggv[NL*DD];
__device__ __align__(16) float g_qkv0[7*TD];
__device__ __align__(16) float g_msgN[6*DD];
__device__ __align__(16) float g_aggnraw[DD];
__device__ __align__(16) float g_hid[7*FF];   // [0,FF): up2; [FF,7FF): up1 rows1-6
__device__ __align__(16) float g_yraw[7*DD];  // row0: down2 RAW; rows1-6: down1 (bias+resid incl)
__device__ unsigned long long g_bar;

// ---------------- helpers ----------------
__device__ __forceinline__ float wred(float v) {
#pragma unroll
    for (int o = 16; o; o >>= 1) v += __shfl_xor_sync(0xffffffffu, v, o);
    return v;
}
__device__ __forceinline__ float d4(float4 a, float4 b) {
    return fmaf(a.x, b.x, fmaf(a.y, b.y, fmaf(a.z, b.z, a.w * b.w)));
}
__device__ __forceinline__ void gb_arrive() {
    __syncthreads();
    if (threadIdx.x == 0)
        asm volatile("red.release.gpu.add.u64 [%0], %1;" :: "l"(&g_bar), "l"(1ULL) : "memory");
}
__device__ __forceinline__ void gb_wait(unsigned long long base, int idx) {
    if (threadIdx.x == 0) {
        unsigned long long target = base + (unsigned long long)idx * NBLK;
        unsigned long long cur;
        do {
            asm volatile("ld.acquire.gpu.u64 %0, [%1];" : "=l"(cur) : "l"(&g_bar) : "memory");
        } while (cur < target);   // pure spin — no nanosleep quantization
    }
    __syncthreads();
}
// real L2 prefetch (ld.global.cg, dead regs)
__device__ __forceinline__ void pf_ld(const float* base, int nfloats, int gt) {
    const char* p = (const char*)base;
    int nlines = nfloats >> 5;
    for (int i = gt; i < nlines; i += NBLK*NTHR) {
        const char* q = p + (size_t)i*128;
        float a, b, c, d;
        asm volatile(
            "ld.global.cg.f32 %0, [%4];\n\t"
            "ld.global.cg.f32 %1, [%4+32];\n\t"
            "ld.global.cg.f32 %2, [%4+64];\n\t"
            "ld.global.cg.f32 %3, [%4+96];"
            : "=f"(a), "=f"(b), "=f"(c), "=f"(d) : "l"(q));
    }
}
__device__ __forceinline__ void cp4(float* dst, const float* src, int n) {
    float4* d4p = (float4*)dst;
    const float4* s4p = (const float4*)src;
    for (int i = threadIdx.x; i < (n >> 2); i += NTHR) d4p[i] = s4p[i];
}
__device__ __forceinline__ void cp4s(float* dst, const float* src, int n) {
    int nq = n >> 2;
    int off = (int)((blockIdx.x * 61) % nq);
    float4* d4p = (float4*)dst;
    const float4* s4p = (const float4*)src;
    for (int c = threadIdx.x; c < nq; c += NTHR) {
        int j = c + off; if (j >= nq) j -= nq;
        d4p[j] = s4p[j];
    }
}
__device__ __forceinline__ void ldw(const float* w, float4* wv) {
    const float4* wr = (const float4*)w;
    int lane = threadIdx.x & 31;
#pragma unroll
    for (int i = 0; i < 4; i++) wv[i] = __ldg(&wr[lane + 32*i]);
}
template<int K, int STR>
__device__ __forceinline__ void dotK(const float4* wv, const float* smbase, float* res) {
    int lane = threadIdx.x & 31;
    float acc[K];
#pragma unroll
    for (int k = 0; k < K; k++) {
        const float4* s4 = (const float4*)(smbase + k*STR);
        float a0 = d4(wv[0], s4[lane]);
        float a1 = d4(wv[1], s4[lane+32]);
        float a2 = d4(wv[2], s4[lane+64]);
        float a3 = d4(wv[3], s4[lane+96]);
        acc[k] = (a0 + a1) + (a2 + a3);
    }
#pragma unroll
    for (int o = 16; o; o >>= 1)
#pragma unroll
        for (int k = 0; k < K; k++)
            acc[k] += __shfl_xor_sync(0xffffffffu, acc[k], o);
#pragma unroll
    for (int k = 0; k < K; k++) res[k] = acc[k];
}
// dot of 512-float weight row vs 512-float activation, BOTH from global (L2),
// loads issued in parallel (no smem staging round trip)
__device__ __forceinline__ float dot1g(const float* w, const float* act) {
    int lane = threadIdx.x & 31;
    const float4* wr = (const float4*)w;
    const float4* ar = (const float4*)act;
    float4 wv0 = __ldg(&wr[lane]),    wv1 = __ldg(&wr[lane+32]);
    float4 wv2 = __ldg(&wr[lane+64]), wv3 = __ldg(&wr[lane+96]);
    float4 av0 = __ldg(&ar[lane]),    av1 = __ldg(&ar[lane+32]);
    float4 av2 = __ldg(&ar[lane+64]), av3 = __ldg(&ar[lane+96]);
    float a0 = d4(wv0, av0), a1 = d4(wv1, av1);
    float a2 = d4(wv2, av2), a3 = d4(wv3, av3);
    return wred((a0 + a1) + (a2 + a3));
}
template<int NIT>
__device__ __forceinline__ float dot_long(const float* w, const float* smbase) {
    int lane = threadIdx.x & 31;
    const float4* wr = (const float4*)w;
    const float4* s4 = (const float4*)smbase;
    float a[4] = {0.f, 0.f, 0.f, 0.f};
#pragma unroll
    for (int i = 0; i < NIT; i += 4) {
        a[0] += d4(__ldg(&wr[lane + 32*(i+0)]), s4[lane + 32*(i+0)]);
        a[1] += d4(__ldg(&wr[lane + 32*(i+1)]), s4[lane + 32*(i+1)]);
        a[2] += d4(__ldg(&wr[lane + 32*(i+2)]), s4[lane + 32*(i+2)]);
        a[3] += d4(__ldg(&wr[lane + 32*(i+3)]), s4[lane + 32*(i+3)]);
    }
    return wred((a[0] + a[1]) + (a[2] + a[3]));
}
template<typename G>
__device__ __forceinline__ void ln_rowf(G get, const float* __restrict__ w,
                                        const float* __restrict__ b,
                                        float* __restrict__ out) {
    int lane = threadIdx.x & 31;
    float v[16]; float s = 0.f;
#pragma unroll
    for (int j = 0; j < 16; j++) { v[j] = get(j*32 + lane); s += v[j]; }
    s = wred(s);
    float mu = s * (1.f/512.f);
    float q = 0.f;
#pragma unroll
    for (int j = 0; j < 16; j++) { float d = v[j] - mu; q += d*d; }
    q = wred(q);
    float rs = rsqrtf(q * (1.f/512.f) + 1e-5f);
#pragma unroll
    for (int j = 0; j < 16; j++)
        out[j*32 + lane] = (v[j] - mu) * rs * w[j*32 + lane] + b[j*32 + lane];
}

__global__ void __launch_bounds__(NTHR, 1)
fused_kernel(const float* __restrict__ feat, const float* __restrict__ role,
             const float* __restrict__ in_w, const float* __restrict__ in_b,
             const float* __restrict__ out_w, const float* __restrict__ out_b,
             const float* __restrict__ ln1w, const float* __restrict__ ln1b,
             const float* __restrict__ ln2w, const float* __restrict__ ln2b,
             const float* __restrict__ ln3w, const float* __restrict__ ln3b,
             const float* __restrict__ ln4w, const float* __restrict__ ln4b,
             const float* __restrict__ f1w1, const float* __restrict__ f1b1,
             const float* __restrict__ f1w2, const float* __restrict__ f1b2,
             const float* __restrict__ f2w1, const float* __restrict__ f2b1,
             const float* __restrict__ f2w2, const float* __restrict__ f2b2,
             const float* __restrict__ a1w, const float* __restrict__ a1b,
             const float* __restrict__ a2w, const float* __restrict__ a2b,
             float* __restrict__ out)
{
    extern __shared__ float sm[];
    float* psx   = sm;            // 7*512 persistent x rows
    float* psh1  = sm + 3584;     // 6*512 LN1 output
    float* psh0  = sm + 6656;     // 512   LN3 output
    float* srole = sm + 7168;     // 6*512 persistent role rows (batch 0)
    float* saggv = sm + 10240;    // 6*512 persistent aggv (all layers)
    float* sc    = sm + 13312;    // layer-loop scratch (14336 floats)
    float* scp   = sm + 7168;     // preamble scratch (clobbers srole/saggv)
    const int tid = threadIdx.x, lane = tid & 31, warp = tid >> 5;
    const int bid = blockIdx.x;
    const int gw = bid * NWPC + warp;
    const int gt = bid * NTHR + tid;

    unsigned long long bbase = 0;
    if (tid == 0) {
        unsigned long long cur;
        asm volatile("ld.relaxed.gpu.u64 %0, [%1];" : "=l"(cur) : "l"(&g_bar));
        bbase = cur - (cur % (NBAR * (unsigned long long)NBLK));
    }
    int bi = 0;

    // ---- Phase A: src for batches 1..5 ----
    for (int i = gt; i < 35*DD; i += NBLK*NTHR) {
        int b5 = i / (7*DD); int rem = i % (7*DD); int s = rem / DD; int d = rem % DD;
        float v = feat[((b5+1)*7 + s)*DD + d];
        if (s > 0) v += role[((b5+1)*6 + (s-1))*DD + d];
        g_src35[i] = v;
    }
    gb_arrive();
    pf_ld(in_w, NL*TD*DD, gt);
    gb_wait(bbase, ++bi);

    // ---- P1: K,V for (l,b>=1,s) and Q(token0) ----
    cp4s(scp, g_src35, 35*DD);
    __syncthreads();
    for (int t = gw; t < NL*1024 + NL*DD; t += NWARP) {
        float4 wv[4];
        {
            const float* rp = (t < NL*1024)
                ? in_w + ((size_t)(t >> 10)*TD + 512 + (t & 1023))*DD
                : in_w + ((size_t)((t - NL*1024) >> 9)*TD + ((t - NL*1024) & 511))*DD;
            ldw(rp, wv);
        }
        if (t < NL*1024) {
            int l = t >> 10, e = t & 1023;
            float bias = in_b[l*TD + 512 + e];
            float res[7];
#pragma unroll
            for (int g = 0; g < 5; g++) {
                dotK<7, DD>(wv, scp + g*7*DD, res);
                if (lane == 0)
#pragma unroll
                    for (int j = 0; j < 7; j++)
                        g_kv[((size_t)(l*5 + g)*7 + j)*1024 + e] = res[j] + bias;
            }
        } else {
            int t2 = t - NL*1024;
            int l = t2 >> 9, e = t2 & 511;
            float bias = in_b[l*TD + e];
            float res[5];
            dotK<5, 7*DD>(wv, scp, res);
            if (lane == 0)
#pragma unroll
                for (int j = 0; j < 5; j++)
                    g_q0[(l*5 + j)*DD + e] = res[j] + bias;
        }
    }
    gb_arrive();
    pf_ld(out_w, NL*DD*DD, gt);
    pf_ld(a1w, NL*DD*2560, gt);
    gb_wait(bbase, ++bi);

    // ---- P2a: attention token0 for (l, b>=1): 30 CTA tasks ----
    if (bid < 30) {
        int l = bid / 5, b5 = bid % 5;
        float* sq = scp; float* sk = scp + DD; float* satt = scp + DD + 7*DD;
        const float* kvb = g_kv + (size_t)(l*5 + b5)*7*1024;
        cp4(sq, g_q0 + (l*5 + b5)*DD, DD);
        for (int i = tid; i < 7*DD; i += NTHR) { int s = i >> 9, d = i & 511; sk[i] = kvb[s*1024 + d]; }
        __syncthreads();
        if (tid < 56) {
            int h = tid / 7, s = tid % 7;
            float a = 0.f;
            for (int d = 0; d < 64; d++) a += sq[h*64 + d] * sk[s*DD + h*64 + d];
            satt[tid] = a * 0.125f;
        }
        __syncthreads();
        if (tid < 8) {
            float m = -1e30f;
            for (int s = 0; s < 7; s++) m = fmaxf(m, satt[tid*7 + s]);
            float e[7], su = 0.f;
            for (int s = 0; s < 7; s++) { e[s] = expf(satt[tid*7 + s] - m); su += e[s]; }
            for (int s = 0; s < 7; s++) satt[tid*7 + s] = e[s] / su;
        }
        __syncthreads();
        for (int ch = tid; ch < DD; ch += NTHR) {
            int h = ch >> 6;
            float a = 0.f;
            for (int s = 0; s < 7; s++) a += satt[h*7 + s] * kvb[s*1024 + 512 + ch];
            g_ctx5[(l*5 + b5)*DD + ch] = a;
        }
    }
    gb_arrive();
    gb_wait(bbase, ++bi);

    // ---- P2b: verb msgs ----
    cp4s(scp, g_ctx5, 30*DD);
    __syncthreads();
    for (int t = gw; t < NL*DD; t += NWARP) {
        float4 wv[4];
        ldw(out_w + ((size_t)(t >> 9)*DD + (t & 511))*DD, wv);
        int l = t >> 9, e = t & 511;
        float bias = out_b[t];
        float res[5];
        dotK<5, DD>(wv, scp + l*5*DD, res);
        if (lane == 0)
#pragma unroll
            for (int j = 0; j < 5; j++)
                g_vm[(l*5 + j)*DD + e] = res[j] + bias;
    }
    gb_arrive();
    gb_wait(bbase, ++bi);

    // ---- P3: agg_verb ----
    cp4s(scp, g_vm, 30*DD);
    __syncthreads();
    for (int t = gw; t < NL*DD; t += NWARP) {
        int l = t >> 9, e = t & 511;
        float a = dot_long<20>(a1w + ((size_t)l*DD + e)*2560, scp + l*5*DD);
        if (lane == 0) g_aggv[l*DD + e] = 1.f / (1.f + expf(-(a + a1b[l*DD + e])));
    }
    gb_arrive();
    pf_ld(f1w1, FF*DD, gt);
    gb_wait(bbase, ++bi);

    // ---- load persistent smem state (psx, role, aggv) ----
    cp4(psx, feat, 7*DD);
    cp4s(srole, role, 6*DD);
    cp4s(saggv, g_aggv, NL*DD);
    __syncthreads();

    // ================= layer loop =================
    for (int l = 0; l < NL; l++) {
        // ---- F1: LN builds + qkv (all 7 tokens) + up1 ----
        {
            float* ssrc = sc;   // 7*512
            if (warp == 0) {
                if (l == 0) {
                    for (int j = 0; j < 16; j++) ssrc[j*32 + lane] = psx[j*32 + lane];
                } else {
                    const float* fb = f2b2 + (l-1)*DD;
                    ln_rowf([&](int i){ return g_yraw[i] + fb[i] + psh0[i]; },
                            ln4w + (l-1)*DD, ln4b + (l-1)*DD, ssrc);
                    for (int j = 0; j < 16; j++) psx[j*32 + lane] = ssrc[j*32 + lane];
                }
            } else if (warp < 7) {
                ln_rowf([&](int i){ return psx[warp*DD + i] + saggv[l*DD + i]; },
                        ln1w + l*DD, ln1b + l*DD, psh1 + (warp-1)*DD);
            } else if (warp < 13) {
                int r = warp - 6;   // 1..6
                for (int j = 0; j < 16; j++) {
                    int d = j*32 + lane;
                    ssrc[r*DD + d] = psx[r*DD + d] + srole[(r-1)*DD + d];
                }
            } else if (warp < 16) {
                int base = (warp - 13) * 1024;
                for (int j = 0; j < 32; j++) g_yraw[DD + base + j*32 + lane] = 0.f;
            }
            __syncthreads();
            for (int t = gw; t < TD + FF; t += NWARP) {
                float4 wv[4];
                {
                    const float* rp = (t < TD) ? in_w + ((size_t)l*TD + t)*DD
                                               : f1w1 + ((size_t)l*FF + (t - TD))*DD;
                    ldw(rp, wv);
                }
                if (t < TD) {
                    float res[7];
                    dotK<7, DD>(wv, ssrc, res);
                    if (lane == 0) {
                        float bias = in_b[l*TD + t];
#pragma unroll
                        for (int s = 0; s < 7; s++) g_qkv0[s*TD + t] = res[s] + bias;
                    }
                } else {
                    int e = t - TD;
                    float res[6];
                    dotK<6, DD>(wv, psh1, res);
                    if (lane == 0) {
                        float bias = f1b1[l*FF + e];
#pragma unroll
                        for (int r = 0; r < 6; r++)
                            g_hid[(r+1)*FF + e] = fmaxf(res[r] + bias, 0.f);
                    }
                }
            }
        }
        gb_arrive();
        pf_ld(a2w + (size_t)l*DD*3072, DD*3072, gt);
        pf_ld(f1w2 + (size_t)l*DD*FF, DD*FF, gt);
        gb_wait(bbase, ++bi);

        // ---- F2: attention + msg (CTAs 0-31) | down1 (CTAs 32+, 1-seg loads) ----
        {
            if (bid < 32) {
                float* sqkv = sc;            // 10752
                float* sctx = sc + 10752;    // 3072
                float* satt = sc + 13824;    // 336
                cp4s(sqkv, g_qkv0, 7*TD);
                __syncthreads();
                for (int t = tid; t < 336; t += NTHR) {
                    int qi = t / 56, r = t % 56, h = r / 7, s = r % 7;
                    const float* qv = sqkv + (qi+1)*TD + h*64;
                    const float* kv = sqkv + s*TD + 512 + h*64;
                    float a0=0,a1=0,a2=0,a3=0;
#pragma unroll
                    for (int d = 0; d < 64; d += 4) {
                        a0 = fmaf(qv[d],   kv[d],   a0);
                        a1 = fmaf(qv[d+1], kv[d+1], a1);
                        a2 = fmaf(qv[d+2], kv[d+2], a2);
                        a3 = fmaf(qv[d+3], kv[d+3], a3);
                    }
                    satt[t] = ((a0+a1)+(a2+a3)) * 0.125f;
                }
                __syncthreads();
                if (tid < 48) {
                    float m = -1e30f;
                    for (int s = 0; s < 7; s++) m = fmaxf(m, satt[tid*7 + s]);
                    float e[7], su = 0.f;
                    for (int s = 0; s < 7; s++) { e[s] = expf(satt[tid*7 + s] - m); su += e[s]; }
                    for (int s = 0; s < 7; s++) satt[tid*7 + s] = e[s] / su;
                }
                __syncthreads();
                for (int i = tid; i < 6*DD; i += NTHR) {
                    int qi = i >> 9, ch = i & 511, h = ch >> 6;
                    float a = 0.f;
                    for (int s = 0; s < 7; s++) a += satt[qi*56 + h*7 + s] * sqkv[s*TD + 1024 + ch];
                    sctx[i] = a;
                }
                __syncthreads();
                if (warp < 16) {
                    int t = bid * 16 + warp;   // 0..511
                    float4 wv[4];
                    ldw(out_w + ((size_t)l*DD + t)*DD, wv);
                    float res[6];
                    dotK<6, DD>(wv, sctx, res);
                    if (lane == 0) {
                        float bias = out_b[l*DD + t];
#pragma unroll
                        for (int r = 0; r < 6; r++) g_msgN[r*DD + t] = res[r] + bias;
                    }
                }
            } else {
                // down1: CTA (bid-32) covers u in [u0, u0+32) — single segment s0
                float* shloc = sc;   // 6*512
                int u0 = (bid - 32) * NWPC;
                int s0 = u0 >> 9;
                if (u0 < 2048) {
                    for (int i = tid; i < 6*512; i += NTHR) {
                        int r = i >> 9, d = i & 511;
                        shloc[i] = g_hid[FF + r*FF + s0*512 + d];
                    }
                }
                if (bid == 140)
                    for (int i = tid; i < DD; i += NTHR) g_aggnraw[i] = 0.f;
                __syncthreads();
                int u = u0 + warp;
                if (u < 2048) {
                    int e = u & 511;
                    float4 wv[4];
                    ldw(f1w2 + ((size_t)l*DD + e)*FF + s0*512, wv);
                    float res[6];
                    dotK<6, 512>(wv, shloc, res);
                    if (lane == 0) {
                        float extra = (s0 == 0) ? f1b2[l*DD + e] : 0.f;
#pragma unroll
                        for (int r = 0; r < 6; r++) {
                            float add = res[r] + ((s0 == 0) ? (extra + psh1[r*DD + e]) : 0.f);
                            atomicAdd(&g_yraw[(r+1)*DD + e], add);
                        }
                    }
                }
            }
        }
        gb_arrive();
        pf_ld(f2w1 + (size_t)l*FF*DD, FF*DD, gt);
        gb_wait(bbase, ++bi);

        // ---- F3: aggn (direct-global act reads, no staging); zero yraw row0 ----
        {
            if (bid == 140)
                for (int i = tid; i < DD; i += NTHR) g_yraw[i] = 0.f;
            int u = gw;
            if (u < 3072) {
                int e = u & 511, s0 = u >> 9;
                float a = dot1g(a2w + ((size_t)l*DD + e)*3072 + s0*512,
                                g_msgN + s0*512);
                if (lane == 0) atomicAdd(&g_aggnraw[e], a);
            }
        }
        gb_arrive();
        if (l + 1 < NL) pf_ld(in_w + (size_t)(l+1)*TD*DD, TD*DD, gt);
        gb_wait(bbase, ++bi);

        // ---- F4: LN3 + LN2 + up2 ----
        {
            if (warp == 0) {
                const float* ab = a2b + l*DD;
                ln_rowf([&](int i){
                            float a = g_aggnraw[i] + ab[i];
                            return psx[i] + 1.f / (1.f + expf(-a));
                        }, ln3w + l*DD, ln3b + l*DD, psh0);
            } else if (warp < 7) {
                ln_rowf([&](int i){ return g_yraw[warp*DD + i]; },
                        ln2w + l*DD, ln2b + l*DD, psx + warp*DD);
            }
            __syncthreads();
            for (int t = gw; t < FF; t += NWARP) {
                float4 wv[4];
                ldw(f2w1 + ((size_t)l*FF + t)*DD, wv);
                float res[1];
                dotK<1, DD>(wv, psh0, res);
                if (lane == 0) g_hid[t] = fmaxf(res[0] + f2b1[l*FF + t], 0.f);
            }
        }
        gb_arrive();
        pf_ld(f2w2 + (size_t)l*DD*FF, DD*FF, gt);
        gb_wait(bbase, ++bi);

        // ---- F5: down2 (direct-global act reads, RAW partials) ----
        {
            int u = gw;
            if (u < 2048) {
                int e = u & 511, s0 = u >> 9;
                float a = dot1g(f2w2 + ((size_t)l*DD + e)*FF + s0*512,
                                g_hid + s0*512);
                if (lane == 0) atomicAdd(&g_yraw[e], a);
            }
        }
        gb_arrive();
        if (l + 1 < NL) pf_ld(f1w1 + (size_t)(l+1)*FF*DD, FF*DD, gt);
        gb_wait(bbase, ++bi);
    }

    // ---- final output: LN4 row0, LN2 rows1-6 ----
    if (bid == 0 && warp < 7) {
        if (warp == 0) {
            const float* fb = f2b2 + 5*DD;
            ln_rowf([&](int i){ return g_yraw[i] + fb[i] + psh0[i]; },
                    ln4w + 5*DD, ln4b + 5*DD, out);
        } else {
            ln_rowf([&](int i){ return g_yraw[warp*DD + i]; },
                    ln2w + 5*DD, ln2b + 5*DD, out + warp*DD);
        }
    }
}

#define SMEM_BYTES 110592

extern "C" void kernel_launch(void* const* d_in, const int* in_sizes, int n_in,
                              void* d_out, int out_size) {
    cudaFuncSetAttribute(fused_kernel, cudaFuncAttributeMaxDynamicSharedMemorySize, SMEM_BYTES);
    fused_kernel<<<NBLK, NTHR, SMEM_BYTES>>>(
        (const float*)d_in[0],  (const float*)d_in[1],
        (const float*)d_in[2],  (const float*)d_in[3],
        (const float*)d_in[4],  (const float*)d_in[5],
        (const float*)d_in[6],  (const float*)d_in[7],
        (const float*)d_in[8],  (const float*)d_in[9],
        (const float*)d_in[10], (const float*)d_in[11],
        (const float*)d_in[12], (const float*)d_in[13],
        (const float*)d_in[14], (const float*)d_in[15],
        (const float*)d_in[16], (const float*)d_in[17],
        (const float*)d_in[18], (const float*)d_in[19],
        (const float*)d_in[20], (const float*)d_in[21],
        (const float*)d_in[22], (const float*)d_in[23],
        (const float*)d_in[24], (const float*)d_in[25],
        (float*)d_out);
}